// round 3
// baseline (speedup 1.0000x reference)
#include <cuda_runtime.h>
#include <cuda_bf16.h>
#include <cstdint>

#define MAX_N 100000
#define DIM   160
#define NS    64
#define NV    32

typedef unsigned long long ull;

// ---- device scratch (no allocs allowed) ----
__device__ __align__(16) float g_msg[MAX_N * DIM];  // 64 MB segment-sum buffer
// Weight matrices pre-paired along K: element [u2][o] = {W[2*u2][o], W[2*u2+1][o]}
__device__ __align__(16) ull g_Wcs2[96 * 96];   // s-path   (K=192)
__device__ __align__(16) ull g_Wc1p[64 * 32];   // v-path 1 (K=128)
__device__ __align__(16) ull g_Wc2p[32 * 32];   // v-path 2 (K=64)

__device__ __forceinline__ ull pack2(float lo, float hi) {
    return (ull)__float_as_uint(lo) | ((ull)__float_as_uint(hi) << 32);
}
__device__ __forceinline__ float hsum2(ull v) {
    return __uint_as_float((unsigned)v) + __uint_as_float((unsigned)(v >> 32));
}
#define FMA2(acc, a, b) \
    asm("fma.rn.f32x2 %0, %1, %2, %3;" : "=l"(acc) : "l"(a), "l"(b), "l"(acc))

// ---------------------------------------------------------------------------
// Kernel 1: fold scale factors / tp-weight vectors into combined, K-paired mats
// ---------------------------------------------------------------------------
__device__ __forceinline__ float comb_s(int u, int o,
                                        const float* Wls, const float* W000,
                                        const float* W110, const float* w00,
                                        const float* w11) {
    const float inv_fan = rsqrtf(96.f);
    const float inv2 = rsqrtf(2.f);
    if (u < 64)  return Wls[u * 96 + o] * inv_fan * w00[u];
    if (u < 96)  return Wls[u * 96 + o] * inv_fan * w11[u - 64];
    if (u < 160) return W000[(u - 96) * 96 + o] * inv2 * rsqrtf(64.f);
    return W110[(u - 160) * 96 + o] * inv2 * rsqrtf(32.f);
}
__device__ __forceinline__ float comb_1(int u, int o,
                                        const float* Wlv, const float* W011,
                                        const float* w01) {
    const float inv_fan = rsqrtf(96.f);
    const float inv2 = rsqrtf(2.f);
    if (u < 64) return Wlv[u * 32 + o] * inv_fan * w01[u];
    return W011[(u - 64) * 32 + o] * inv2 * rsqrtf(64.f);
}
__device__ __forceinline__ float comb_2(int u, int o,
                                        const float* Wlv, const float* W101,
                                        const float* w10) {
    const float inv_fan = rsqrtf(96.f);
    const float inv2 = rsqrtf(2.f);
    if (u < 32) return Wlv[(64 + u) * 32 + o] * inv_fan * w10[u];
    return W101[(u - 32) * 32 + o] * inv2 * rsqrtf(32.f);
}

__global__ void prep_weights(const float* __restrict__ Wls,
                             const float* __restrict__ Wlv,
                             const float* __restrict__ W000,
                             const float* __restrict__ W110,
                             const float* __restrict__ W011,
                             const float* __restrict__ W101,
                             const float* __restrict__ w00,
                             const float* __restrict__ w01,
                             const float* __restrict__ w10,
                             const float* __restrict__ w11)
{
    int i = blockIdx.x * blockDim.x + threadIdx.x;
    if (i < 96 * 96) {
        int u2 = i / 96, o = i - u2 * 96;
        g_Wcs2[i] = pack2(comb_s(2 * u2, o, Wls, W000, W110, w00, w11),
                          comb_s(2 * u2 + 1, o, Wls, W000, W110, w00, w11));
    } else if (i < 96 * 96 + 64 * 32) {
        int j = i - 96 * 96;
        int u2 = j / 32, o = j - u2 * 32;
        g_Wc1p[j] = pack2(comb_1(2 * u2, o, Wlv, W011, w01),
                          comb_1(2 * u2 + 1, o, Wlv, W011, w01));
    } else if (i < 96 * 96 + 64 * 32 + 32 * 32) {
        int j = i - (96 * 96 + 64 * 32);
        int u2 = j / 32, o = j - u2 * 32;
        g_Wc2p[j] = pack2(comb_2(2 * u2, o, Wlv, W101, w10),
                          comb_2(2 * u2 + 1, o, Wlv, W101, w10));
    }
}

// ---------------------------------------------------------------------------
// Kernel 2: zero the segment-sum buffer
// ---------------------------------------------------------------------------
__global__ void zero_msg(int n4)
{
    int i = blockIdx.x * blockDim.x + threadIdx.x;
    if (i < n4) reinterpret_cast<float4*>(g_msg)[i] = make_float4(0.f, 0.f, 0.f, 0.f);
}

// ---------------------------------------------------------------------------
// Kernel 3: scatter-add edge messages with vectorized global reductions
// ---------------------------------------------------------------------------
__global__ void scatter_edges(const float4* __restrict__ em,
                              const int*    __restrict__ eidx,
                              int E)
{
    int i = blockIdx.x * blockDim.x + threadIdx.x;
    if (i >= E * 40) return;
    int e = i / 40;
    int j = i - e * 40;
    float4 v = em[i];
    int dst  = __ldg(eidx + E + e);
    float* p = g_msg + (size_t)dst * DIM + j * 4;
    asm volatile("red.global.add.v4.f32 [%0], {%1, %2, %3, %4};"
                 :: "l"(p), "f"(v.x), "f"(v.y), "f"(v.z), "f"(v.w)
                 : "memory");
}

// ---------------------------------------------------------------------------
// Kernel 4: fused per-node update. 256 threads = 8 warps, 64 nodes/block,
// M=8 nodes per warp. U staged pair-interleaved so one broadcast LDS.128
// feeds the K-pair operand of TWO nodes:
//   sU[pair][u2][4] = { n_even[2u2], n_even[2u2+1], n_odd[2u2], n_odd[2u2+1] }
// Weights streamed via __ldg (L1-resident, ~96 KB); node data via __ldcs.
// Per-node logical U indices (0..511):
//   [  0:192) U_s  = [a_s*ms | (mv.a_v)/sqrt3 | a_s*xs | (xv.a_v)/sqrt3]
//   [192:320) U_1  = [ms | xs]
//   [320:512) U_2  = for c in 0..2: [a_s*mv[:,c] (32) | a_s*xv[:,c] (32)]
// ---------------------------------------------------------------------------
__device__ __forceinline__ int uaddr(int slot, int k) {
    // pair*1024 + u2*4 + (k&1) + 2*(slot&1)
    return ((slot >> 1) << 10) + ((k >> 1) << 2) + (k & 1) + ((slot & 1) << 1);
}

__global__ void __launch_bounds__(256, 1)
node_update(const float* __restrict__ feats,
            const float* __restrict__ attrs,
            float*       __restrict__ out,
            int N)
{
    extern __shared__ __align__(16) float sm[];
    float* sU  = sm;              // 32 pairs * 1024 floats = 131072 B
    float* sAv = sm + 32 * 1024;  // 64 * 3

    const float rs5  = 0.44721359549995794f;  // 1/sqrt(5)
    const float inv3 = 0.5773502691896258f;   // 1/sqrt(3)

    const int t    = threadIdx.x;
    const int base = blockIdx.x * 64;

    // ---- prologue: build U vectors (4 threads per node) ----
    {
        int i  = t >> 2;          // node slot 0..63
        int t4 = t & 3;
        int n  = base + i;
        if (n < N) {
            float a0  = __ldg(attrs + n * 4 + 0);
            float av0 = __ldg(attrs + n * 4 + 1);
            float av1 = __ldg(attrs + n * 4 + 2);
            float av2 = __ldg(attrs + n * 4 + 3);
            if (t4 == 0) {
                sAv[i * 3 + 0] = av0; sAv[i * 3 + 1] = av1; sAv[i * 3 + 2] = av2;
            }
            const float* mrow = g_msg + (size_t)n * DIM;
            const float* frow = feats + (size_t)n * DIM;
            #pragma unroll 4
            for (int k = t4; k < 64; k += 4) {
                float ms = __ldcs(mrow + k) * rs5;
                float xs = __ldcs(frow + k);
                sU[uaddr(i, k)]       = a0 * ms;
                sU[uaddr(i, 96 + k)]  = a0 * xs;
                sU[uaddr(i, 192 + k)] = ms;
                sU[uaddr(i, 256 + k)] = xs;
            }
            #pragma unroll 2
            for (int k = t4; k < 32; k += 4) {
                float m0 = __ldcs(mrow + 64 + k * 3 + 0) * rs5;
                float m1 = __ldcs(mrow + 64 + k * 3 + 1) * rs5;
                float m2 = __ldcs(mrow + 64 + k * 3 + 2) * rs5;
                float x0 = __ldcs(frow + 64 + k * 3 + 0);
                float x1 = __ldcs(frow + 64 + k * 3 + 1);
                float x2 = __ldcs(frow + 64 + k * 3 + 2);
                sU[uaddr(i, 64 + k)]  = (m0 * av0 + m1 * av1 + m2 * av2) * inv3;
                sU[uaddr(i, 160 + k)] = (x0 * av0 + x1 * av1 + x2 * av2) * inv3;
                sU[uaddr(i, 320 + k)]       = a0 * m0;
                sU[uaddr(i, 320 + 64 + k)]  = a0 * m1;
                sU[uaddr(i, 320 + 128 + k)] = a0 * m2;
                sU[uaddr(i, 352 + k)]       = a0 * x0;
                sU[uaddr(i, 352 + 64 + k)]  = a0 * x1;
                sU[uaddr(i, 352 + 128 + k)] = a0 * x2;
            }
        } else {
            #pragma unroll 8
            for (int k = t4; k < 512; k += 4) sU[uaddr(i, k)] = 0.f;
            if (t4 == 0) { sAv[i*3] = 0.f; sAv[i*3+1] = 0.f; sAv[i*3+2] = 0.f; }
        }
    }
    __syncthreads();

    const int lane   = t & 31;
    const int pb     = (t >> 5) * 4;   // first pair index for this warp (4 pairs = 8 nodes)
    const int nvalid = N - base;

    // ---- s-path GEMM: h_s[96] = U_s[192] . Wc_s[192][96] ----
    ull A0[8], A1[8], A2[8];
    #pragma unroll
    for (int m = 0; m < 8; m++) { A0[m] = 0ull; A1[m] = 0ull; A2[m] = 0ull; }

    #pragma unroll 2
    for (int u2 = 0; u2 < 96; ++u2) {
        ull w0 = __ldg(g_Wcs2 + u2 * 96 + lane);
        ull w1 = __ldg(g_Wcs2 + u2 * 96 + 32 + lane);
        ull w2 = __ldg(g_Wcs2 + u2 * 96 + 64 + lane);
        #pragma unroll
        for (int p = 0; p < 4; ++p) {
            ulonglong2 b = *(const ulonglong2*)(sU + ((pb + p) << 10) + (u2 << 2));
            FMA2(A0[2*p],   b.x, w0);
            FMA2(A1[2*p],   b.x, w1);
            FMA2(A2[2*p],   b.x, w2);
            FMA2(A0[2*p+1], b.y, w0);
            FMA2(A1[2*p+1], b.y, w1);
            FMA2(A2[2*p+1], b.y, w2);
        }
    }

    // s epilogue: silu on first 64 outputs, sigmoid gates kept in regs
    float g[8];
    #pragma unroll
    for (int m = 0; m < 8; m++) {
        float h0 = hsum2(A0[m]);
        float h1 = hsum2(A1[m]);
        float h2 = hsum2(A2[m]);
        g[m] = 1.f / (1.f + __expf(-h2));
        if (pb * 2 + m < nvalid) {
            float* orow = out + (size_t)(base + pb * 2 + m) * DIM;
            __stcs(orow + lane,      h0 / (1.f + __expf(-h0)));
            __stcs(orow + lane + 32, h1 / (1.f + __expf(-h1)));
        }
    }

    // ---- v-path GEMM 1: G1[32] = U_1[128] . Wc_1[128][32] (u2 96..159) ----
    ull V[8];
    #pragma unroll
    for (int m = 0; m < 8; m++) V[m] = 0ull;
    #pragma unroll 2
    for (int j = 0; j < 64; ++j) {
        ull wv = __ldg(g_Wc1p + j * 32 + lane);
        #pragma unroll
        for (int p = 0; p < 4; ++p) {
            ulonglong2 b = *(const ulonglong2*)(sU + ((pb + p) << 10) + ((96 + j) << 2));
            FMA2(V[2*p],   b.x, wv);
            FMA2(V[2*p+1], b.y, wv);
        }
    }

    // ---- v-path GEMM 2: G2[32][c] = U_2c[64] . Wc_2[64][32] (u2 160..255) ----
    ull P0[8], P1[8], P2[8];
    #pragma unroll
    for (int m = 0; m < 8; m++) { P0[m] = 0ull; P1[m] = 0ull; P2[m] = 0ull; }
    #pragma unroll 2
    for (int j = 0; j < 32; ++j) {
        ull wv = __ldg(g_Wc2p + j * 32 + lane);
        #pragma unroll
        for (int p = 0; p < 4; ++p) {
            const float* bbase = sU + ((pb + p) << 10);
            ulonglong2 b0 = *(const ulonglong2*)(bbase + ((160 + j) << 2));
            ulonglong2 b1 = *(const ulonglong2*)(bbase + ((192 + j) << 2));
            ulonglong2 b2 = *(const ulonglong2*)(bbase + ((224 + j) << 2));
            FMA2(P0[2*p],   b0.x, wv);
            FMA2(P0[2*p+1], b0.y, wv);
            FMA2(P1[2*p],   b1.x, wv);
            FMA2(P1[2*p+1], b1.y, wv);
            FMA2(P2[2*p],   b2.x, wv);
            FMA2(P2[2*p+1], b2.y, wv);
        }
    }

    // v epilogue: h_v = G1*a_v_c + G2c ; out_v = gate * h_v
    #pragma unroll
    for (int m = 0; m < 8; m++) {
        int slot = pb * 2 + m;
        if (slot < nvalid) {
            float av0 = sAv[slot * 3 + 0];
            float av1 = sAv[slot * 3 + 1];
            float av2 = sAv[slot * 3 + 2];
            float vg  = hsum2(V[m]);
            float* orow = out + (size_t)(base + slot) * DIM + NS + lane * 3;
            __stcs(orow + 0, g[m] * fmaf(vg, av0, hsum2(P0[m])));
            __stcs(orow + 1, g[m] * fmaf(vg, av1, hsum2(P1[m])));
            __stcs(orow + 2, g[m] * fmaf(vg, av2, hsum2(P2[m])));
        }
    }
}

// ---------------------------------------------------------------------------
extern "C" void kernel_launch(void* const* d_in, const int* in_sizes, int n_in,
                              void* d_out, int out_size)
{
    const float* feats = (const float*)d_in[0];
    const float* attrs = (const float*)d_in[1];
    const float* emsg  = (const float*)d_in[2];
    const int*   eidx  = (const int*)  d_in[3];
    const float* w00   = (const float*)d_in[4];
    const float* w01   = (const float*)d_in[5];
    const float* w10   = (const float*)d_in[6];
    const float* w11   = (const float*)d_in[7];
    const float* Wls   = (const float*)d_in[8];
    const float* Wlv   = (const float*)d_in[9];
    const float* W000  = (const float*)d_in[10];
    const float* W110  = (const float*)d_in[11];
    const float* W011  = (const float*)d_in[12];
    const float* W101  = (const float*)d_in[13];

    int N = in_sizes[0] / DIM;
    int E = in_sizes[2] / DIM;

    const int smem_bytes = 32 * 1024 * 4 + 64 * 3 * 4;  // 131840
    cudaFuncSetAttribute(node_update,
                         cudaFuncAttributeMaxDynamicSharedMemorySize, smem_bytes);

    int prep_elems = 96 * 96 + 64 * 32 + 32 * 32;
    prep_weights<<<(prep_elems + 255) / 256, 256>>>(
        Wls, Wlv, W000, W110, W011, W101, w00, w01, w10, w11);

    int n4 = N * (DIM / 4);
    zero_msg<<<(n4 + 255) / 256, 256>>>(n4);

    long total = (long)E * 40;
    scatter_edges<<<(int)((total + 255) / 256), 256>>>(
        (const float4*)emsg, eidx, E);

    int blocks = (N + 63) / 64;
    node_update<<<blocks, 256, smem_bytes>>>(feats, attrs, (float*)d_out, N);
}

// round 4
// speedup vs baseline: 1.3954x; 1.3954x over previous
#include <cuda_runtime.h>
#include <cuda_bf16.h>
#include <cstdint>

#define MAX_N 100000
#define DIM   160
#define NS    64
#define NV    32

typedef unsigned long long ull;

// ---- device scratch (no allocs allowed) ----
__device__ __align__(16) float g_msg[MAX_N * DIM];  // 64 MB segment-sum buffer
// Weight matrices pre-paired along K: element [u2][o] = {W[2*u2][o], W[2*u2+1][o]}
__device__ __align__(16) ull g_Wcs2[96 * 96];   // s-path   (K=192)
__device__ __align__(16) ull g_Wc1p[64 * 32];   // v-path 1 (K=128)
__device__ __align__(16) ull g_Wc2p[32 * 32];   // v-path 2 (K=64)

__device__ __forceinline__ ull pack2(float lo, float hi) {
    return (ull)__float_as_uint(lo) | ((ull)__float_as_uint(hi) << 32);
}
__device__ __forceinline__ float hsum2(ull v) {
    return __uint_as_float((unsigned)v) + __uint_as_float((unsigned)(v >> 32));
}
#define FMA2(acc, a, b) \
    asm("fma.rn.f32x2 %0, %1, %2, %3;" : "=l"(acc) : "l"(a), "l"(b), "l"(acc))

// ---------------------------------------------------------------------------
// Kernel 1: fold scale factors / tp-weight vectors into combined, K-paired mats
// ---------------------------------------------------------------------------
__device__ __forceinline__ float comb_s(int u, int o,
                                        const float* Wls, const float* W000,
                                        const float* W110, const float* w00,
                                        const float* w11) {
    const float inv_fan = rsqrtf(96.f);
    const float inv2 = rsqrtf(2.f);
    if (u < 64)  return Wls[u * 96 + o] * inv_fan * w00[u];
    if (u < 96)  return Wls[u * 96 + o] * inv_fan * w11[u - 64];
    if (u < 160) return W000[(u - 96) * 96 + o] * inv2 * rsqrtf(64.f);
    return W110[(u - 160) * 96 + o] * inv2 * rsqrtf(32.f);
}
__device__ __forceinline__ float comb_1(int u, int o,
                                        const float* Wlv, const float* W011,
                                        const float* w01) {
    const float inv_fan = rsqrtf(96.f);
    const float inv2 = rsqrtf(2.f);
    if (u < 64) return Wlv[u * 32 + o] * inv_fan * w01[u];
    return W011[(u - 64) * 32 + o] * inv2 * rsqrtf(64.f);
}
__device__ __forceinline__ float comb_2(int u, int o,
                                        const float* Wlv, const float* W101,
                                        const float* w10) {
    const float inv_fan = rsqrtf(96.f);
    const float inv2 = rsqrtf(2.f);
    if (u < 32) return Wlv[(64 + u) * 32 + o] * inv_fan * w10[u];
    return W101[(u - 32) * 32 + o] * inv2 * rsqrtf(32.f);
}

__global__ void prep_weights(const float* __restrict__ Wls,
                             const float* __restrict__ Wlv,
                             const float* __restrict__ W000,
                             const float* __restrict__ W110,
                             const float* __restrict__ W011,
                             const float* __restrict__ W101,
                             const float* __restrict__ w00,
                             const float* __restrict__ w01,
                             const float* __restrict__ w10,
                             const float* __restrict__ w11)
{
    int i = blockIdx.x * blockDim.x + threadIdx.x;
    if (i < 96 * 96) {
        int u2 = i / 96, o = i - u2 * 96;
        g_Wcs2[i] = pack2(comb_s(2 * u2, o, Wls, W000, W110, w00, w11),
                          comb_s(2 * u2 + 1, o, Wls, W000, W110, w00, w11));
    } else if (i < 96 * 96 + 64 * 32) {
        int j = i - 96 * 96;
        int u2 = j / 32, o = j - u2 * 32;
        g_Wc1p[j] = pack2(comb_1(2 * u2, o, Wlv, W011, w01),
                          comb_1(2 * u2 + 1, o, Wlv, W011, w01));
    } else if (i < 96 * 96 + 64 * 32 + 32 * 32) {
        int j = i - (96 * 96 + 64 * 32);
        int u2 = j / 32, o = j - u2 * 32;
        g_Wc2p[j] = pack2(comb_2(2 * u2, o, Wlv, W101, w10),
                          comb_2(2 * u2 + 1, o, Wlv, W101, w10));
    }
}

// ---------------------------------------------------------------------------
// Kernel 2: zero the segment-sum buffer (plain stores: keep lines in L2 so the
// scatter atomics and node_update reads hit L2, which holds all 64 MB)
// ---------------------------------------------------------------------------
__global__ void zero_msg(int n4)
{
    int i = blockIdx.x * blockDim.x + threadIdx.x;
    if (i < n4) reinterpret_cast<float4*>(g_msg)[i] = make_float4(0.f, 0.f, 0.f, 0.f);
}

// ---------------------------------------------------------------------------
// Kernel 3: scatter-add edge messages with vectorized global reductions.
// Edge stream is read-once: evict-first so it doesn't push g_msg out of L2.
// ---------------------------------------------------------------------------
__global__ void scatter_edges(const float4* __restrict__ em,
                              const int*    __restrict__ eidx,
                              int E)
{
    int i = blockIdx.x * blockDim.x + threadIdx.x;
    if (i >= E * 40) return;
    int e = i / 40;
    int j = i - e * 40;
    float4 v = __ldcs(em + i);
    int dst  = __ldg(eidx + E + e);
    float* p = g_msg + (size_t)dst * DIM + j * 4;
    asm volatile("red.global.add.v4.f32 [%0], {%1, %2, %3, %4};"
                 :: "l"(p), "f"(v.x), "f"(v.y), "f"(v.z), "f"(v.w)
                 : "memory");
}

// ---------------------------------------------------------------------------
// Kernel 4: fused per-node update. 512 threads = 16 warps, 64 nodes/block,
// M=4 nodes (2 pairs) per warp. U staged pair-interleaved so one broadcast
// LDS.128 feeds the K-pair operand of TWO nodes:
//   sU[pair][u2][4] = { n_even[2u2], n_even[2u2+1], n_odd[2u2], n_odd[2u2+1] }
// Per-node logical U indices (0..511):
//   [  0:192) U_s  = [a_s*ms | (mv.a_v)/sqrt3 | a_s*xs | (xv.a_v)/sqrt3]
//   [192:320) U_1  = [ms | xs]
//   [320:512) U_2  = for c in 0..2: [a_s*mv[:,c] (32) | a_s*xv[:,c] (32)]
// ---------------------------------------------------------------------------
__device__ __forceinline__ int uaddr(int slot, int k) {
    // pair*1024 + u2*4 + (k&1) + 2*(slot&1)
    return ((slot >> 1) << 10) + ((k >> 1) << 2) + (k & 1) + ((slot & 1) << 1);
}

__global__ void __launch_bounds__(512, 1)
node_update(const float* __restrict__ feats,
            const float* __restrict__ attrs,
            float*       __restrict__ out,
            int N)
{
    extern __shared__ __align__(16) float sm[];
    float* sU  = sm;              // 32 pairs * 1024 floats = 131072 B
    float* sAv = sm + 32 * 1024;  // 64 * 3

    const float rs5  = 0.44721359549995794f;  // 1/sqrt(5)
    const float inv3 = 0.5773502691896258f;   // 1/sqrt(3)

    const int t    = threadIdx.x;
    const int base = blockIdx.x * 64;

    // ---- prologue: build U vectors (8 threads per node) ----
    {
        int i  = t >> 3;          // node slot 0..63
        int t8 = t & 7;
        int n  = base + i;
        if (n < N) {
            float a0  = __ldg(attrs + n * 4 + 0);
            float av0 = __ldg(attrs + n * 4 + 1);
            float av1 = __ldg(attrs + n * 4 + 2);
            float av2 = __ldg(attrs + n * 4 + 3);
            if (t8 == 0) {
                sAv[i * 3 + 0] = av0; sAv[i * 3 + 1] = av1; sAv[i * 3 + 2] = av2;
            }
            const float* mrow = g_msg + (size_t)n * DIM;
            const float* frow = feats + (size_t)n * DIM;
            #pragma unroll
            for (int k = t8; k < 64; k += 8) {
                float ms = mrow[k] * rs5;
                float xs = __ldcs(frow + k);
                sU[uaddr(i, k)]       = a0 * ms;
                sU[uaddr(i, 96 + k)]  = a0 * xs;
                sU[uaddr(i, 192 + k)] = ms;
                sU[uaddr(i, 256 + k)] = xs;
            }
            #pragma unroll
            for (int k = t8; k < 32; k += 8) {
                float m0 = mrow[64 + k * 3 + 0] * rs5;
                float m1 = mrow[64 + k * 3 + 1] * rs5;
                float m2 = mrow[64 + k * 3 + 2] * rs5;
                float x0 = __ldcs(frow + 64 + k * 3 + 0);
                float x1 = __ldcs(frow + 64 + k * 3 + 1);
                float x2 = __ldcs(frow + 64 + k * 3 + 2);
                sU[uaddr(i, 64 + k)]  = (m0 * av0 + m1 * av1 + m2 * av2) * inv3;
                sU[uaddr(i, 160 + k)] = (x0 * av0 + x1 * av1 + x2 * av2) * inv3;
                sU[uaddr(i, 320 + k)]       = a0 * m0;
                sU[uaddr(i, 320 + 64 + k)]  = a0 * m1;
                sU[uaddr(i, 320 + 128 + k)] = a0 * m2;
                sU[uaddr(i, 352 + k)]       = a0 * x0;
                sU[uaddr(i, 352 + 64 + k)]  = a0 * x1;
                sU[uaddr(i, 352 + 128 + k)] = a0 * x2;
            }
        } else {
            #pragma unroll
            for (int k = t8; k < 512; k += 8) sU[uaddr(i, k)] = 0.f;
            if (t8 == 0) { sAv[i*3] = 0.f; sAv[i*3+1] = 0.f; sAv[i*3+2] = 0.f; }
        }
    }
    __syncthreads();

    const int lane   = t & 31;
    const int pb     = (t >> 5) * 2;   // first pair index (2 pairs = 4 nodes/warp)
    const int nvalid = N - base;

    // ---- s-path GEMM: h_s[96] = U_s[192] . Wc_s[192][96] ----
    ull A0[4], A1[4], A2[4];
    #pragma unroll
    for (int m = 0; m < 4; m++) { A0[m] = 0ull; A1[m] = 0ull; A2[m] = 0ull; }

    #pragma unroll 4
    for (int u2 = 0; u2 < 96; ++u2) {
        ull w0 = __ldg(g_Wcs2 + u2 * 96 + lane);
        ull w1 = __ldg(g_Wcs2 + u2 * 96 + 32 + lane);
        ull w2 = __ldg(g_Wcs2 + u2 * 96 + 64 + lane);
        #pragma unroll
        for (int p = 0; p < 2; ++p) {
            ulonglong2 b = *(const ulonglong2*)(sU + ((pb + p) << 10) + (u2 << 2));
            FMA2(A0[2*p],   b.x, w0);
            FMA2(A1[2*p],   b.x, w1);
            FMA2(A2[2*p],   b.x, w2);
            FMA2(A0[2*p+1], b.y, w0);
            FMA2(A1[2*p+1], b.y, w1);
            FMA2(A2[2*p+1], b.y, w2);
        }
    }

    // s epilogue: silu on first 64 outputs, sigmoid gates kept in regs
    float g[4];
    #pragma unroll
    for (int m = 0; m < 4; m++) {
        float h0 = hsum2(A0[m]);
        float h1 = hsum2(A1[m]);
        float h2 = hsum2(A2[m]);
        g[m] = 1.f / (1.f + __expf(-h2));
        if (pb * 2 + m < nvalid) {
            float* orow = out + (size_t)(base + pb * 2 + m) * DIM;
            __stcs(orow + lane,      h0 / (1.f + __expf(-h0)));
            __stcs(orow + lane + 32, h1 / (1.f + __expf(-h1)));
        }
    }

    // ---- v-path GEMM 1: G1[32] = U_1[128] . Wc_1[128][32] (u2 96..159) ----
    ull V[4];
    #pragma unroll
    for (int m = 0; m < 4; m++) V[m] = 0ull;
    #pragma unroll 4
    for (int j = 0; j < 64; ++j) {
        ull wv = __ldg(g_Wc1p + j * 32 + lane);
        #pragma unroll
        for (int p = 0; p < 2; ++p) {
            ulonglong2 b = *(const ulonglong2*)(sU + ((pb + p) << 10) + ((96 + j) << 2));
            FMA2(V[2*p],   b.x, wv);
            FMA2(V[2*p+1], b.y, wv);
        }
    }

    // ---- v-path GEMM 2: G2[32][c] = U_2c[64] . Wc_2[64][32] (u2 160..255) ----
    ull P0[4], P1[4], P2[4];
    #pragma unroll
    for (int m = 0; m < 4; m++) { P0[m] = 0ull; P1[m] = 0ull; P2[m] = 0ull; }
    #pragma unroll 4
    for (int j = 0; j < 32; ++j) {
        ull wv = __ldg(g_Wc2p + j * 32 + lane);
        #pragma unroll
        for (int p = 0; p < 2; ++p) {
            const float* bbase = sU + ((pb + p) << 10);
            ulonglong2 b0 = *(const ulonglong2*)(bbase + ((160 + j) << 2));
            ulonglong2 b1 = *(const ulonglong2*)(bbase + ((192 + j) << 2));
            ulonglong2 b2 = *(const ulonglong2*)(bbase + ((224 + j) << 2));
            FMA2(P0[2*p],   b0.x, wv);
            FMA2(P0[2*p+1], b0.y, wv);
            FMA2(P1[2*p],   b1.x, wv);
            FMA2(P1[2*p+1], b1.y, wv);
            FMA2(P2[2*p],   b2.x, wv);
            FMA2(P2[2*p+1], b2.y, wv);
        }
    }

    // v epilogue: h_v = G1*a_v_c + G2c ; out_v = gate * h_v
    #pragma unroll
    for (int m = 0; m < 4; m++) {
        int slot = pb * 2 + m;
        if (slot < nvalid) {
            float av0 = sAv[slot * 3 + 0];
            float av1 = sAv[slot * 3 + 1];
            float av2 = sAv[slot * 3 + 2];
            float vg  = hsum2(V[m]);
            float* orow = out + (size_t)(base + slot) * DIM + NS + lane * 3;
            __stcs(orow + 0, g[m] * fmaf(vg, av0, hsum2(P0[m])));
            __stcs(orow + 1, g[m] * fmaf(vg, av1, hsum2(P1[m])));
            __stcs(orow + 2, g[m] * fmaf(vg, av2, hsum2(P2[m])));
        }
    }
}

// ---------------------------------------------------------------------------
extern "C" void kernel_launch(void* const* d_in, const int* in_sizes, int n_in,
                              void* d_out, int out_size)
{
    const float* feats = (const float*)d_in[0];
    const float* attrs = (const float*)d_in[1];
    const float* emsg  = (const float*)d_in[2];
    const int*   eidx  = (const int*)  d_in[3];
    const float* w00   = (const float*)d_in[4];
    const float* w01   = (const float*)d_in[5];
    const float* w10   = (const float*)d_in[6];
    const float* w11   = (const float*)d_in[7];
    const float* Wls   = (const float*)d_in[8];
    const float* Wlv   = (const float*)d_in[9];
    const float* W000  = (const float*)d_in[10];
    const float* W110  = (const float*)d_in[11];
    const float* W011  = (const float*)d_in[12];
    const float* W101  = (const float*)d_in[13];

    int N = in_sizes[0] / DIM;
    int E = in_sizes[2] / DIM;

    const int smem_bytes = 32 * 1024 * 4 + 64 * 3 * 4;  // 131840
    cudaFuncSetAttribute(node_update,
                         cudaFuncAttributeMaxDynamicSharedMemorySize, smem_bytes);

    int prep_elems = 96 * 96 + 64 * 32 + 32 * 32;
    prep_weights<<<(prep_elems + 255) / 256, 256>>>(
        Wls, Wlv, W000, W110, W011, W101, w00, w01, w10, w11);

    int n4 = N * (DIM / 4);
    zero_msg<<<(n4 + 255) / 256, 256>>>(n4);

    long total = (long)E * 40;
    scatter_edges<<<(int)((total + 255) / 256), 256>>>(
        (const float4*)emsg, eidx, E);

    int blocks = (N + 63) / 64;
    node_update<<<blocks, 512, smem_bytes>>>(feats, attrs, (float*)d_out, N);
}

// round 5
// speedup vs baseline: 2.2549x; 1.6159x over previous
#include <cuda_runtime.h>
#include <cuda_bf16.h>
#include <cstdint>

#define MAX_N 100000
#define DIM     160
#define NS       64
#define NV       32
#define USTRIDE 516   // 64-node U row stride (floats); 516%32=4 -> conflict-free A frags

typedef unsigned long long ull;

// ---- device scratch (no allocs allowed) ----
__device__ __align__(16) float g_msg[MAX_N * DIM];   // 64 MB segment-sum buffer
// Weights pre-packed in m16n8k8 B-fragment order, tf32-rounded.
// Entry [kb][nb][lane] = { W[kb*8 + lane%4][nb*8 + lane/4],
//                          W[kb*8 + lane%4 + 4][nb*8 + lane/4] }
__device__ __align__(16) ull g_Bs[24 * 12 * 32];   // s-path  K=192, O=96
__device__ __align__(16) ull g_B1[16 * 4 * 32];    // v1      K=128, O=32
__device__ __align__(16) ull g_B2[ 8 * 4 * 32];    // v2      K=64,  O=32

__device__ __forceinline__ unsigned tf32r(float x) {
    unsigned r; asm("cvt.rna.tf32.f32 %0, %1;" : "=r"(r) : "f"(x)); return r;
}
__device__ __forceinline__ ull packtf(float lo, float hi) {
    return (ull)tf32r(lo) | ((ull)tf32r(hi) << 32);
}
__device__ __forceinline__ float tf32f(float x) {
    return __uint_as_float(tf32r(x));
}

#define MMA8(d, a0, a1, a2, a3, bb)                                         \
    asm("mma.sync.aligned.m16n8k8.row.col.f32.tf32.tf32.f32 "               \
        "{%0,%1,%2,%3}, {%4,%5,%6,%7}, {%8,%9}, {%0,%1,%2,%3};"             \
        : "+f"(d[0]), "+f"(d[1]), "+f"(d[2]), "+f"(d[3])                    \
        : "r"(a0), "r"(a1), "r"(a2), "r"(a3),                               \
          "r"((unsigned)(bb)), "r"((unsigned)((bb) >> 32)))

// ---------------------------------------------------------------------------
// Combined-weight element generators (fold all norm scalars + tp vectors)
// ---------------------------------------------------------------------------
__device__ __forceinline__ float comb_s(int u, int o,
                                        const float* Wls, const float* W000,
                                        const float* W110, const float* w00,
                                        const float* w11) {
    const float inv_fan = rsqrtf(96.f);
    const float inv2 = rsqrtf(2.f);
    if (u < 64)  return Wls[u * 96 + o] * inv_fan * w00[u];
    if (u < 96)  return Wls[u * 96 + o] * inv_fan * w11[u - 64];
    if (u < 160) return W000[(u - 96) * 96 + o] * inv2 * rsqrtf(64.f);
    return W110[(u - 160) * 96 + o] * inv2 * rsqrtf(32.f);
}
__device__ __forceinline__ float comb_1(int u, int o,
                                        const float* Wlv, const float* W011,
                                        const float* w01) {
    const float inv_fan = rsqrtf(96.f);
    const float inv2 = rsqrtf(2.f);
    if (u < 64) return Wlv[u * 32 + o] * inv_fan * w01[u];
    return W011[(u - 64) * 32 + o] * inv2 * rsqrtf(64.f);
}
__device__ __forceinline__ float comb_2(int u, int o,
                                        const float* Wlv, const float* W101,
                                        const float* w10) {
    const float inv_fan = rsqrtf(96.f);
    const float inv2 = rsqrtf(2.f);
    if (u < 32) return Wlv[(64 + u) * 32 + o] * inv_fan * w10[u];
    return W101[(u - 32) * 32 + o] * inv2 * rsqrtf(32.f);
}

// ---------------------------------------------------------------------------
// Kernel 1: build fragment-ordered, tf32-rounded weight blocks
// ---------------------------------------------------------------------------
__global__ void prep_weights(const float* __restrict__ Wls,
                             const float* __restrict__ Wlv,
                             const float* __restrict__ W000,
                             const float* __restrict__ W110,
                             const float* __restrict__ W011,
                             const float* __restrict__ W101,
                             const float* __restrict__ w00,
                             const float* __restrict__ w01,
                             const float* __restrict__ w10,
                             const float* __restrict__ w11)
{
    int i = blockIdx.x * blockDim.x + threadIdx.x;
    const int NSZ = 24 * 12 * 32;   // 9216
    const int V1Z = 16 * 4 * 32;    // 2048
    const int V2Z = 8 * 4 * 32;     // 1024
    if (i < NSZ) {
        int kb = i / (12 * 32), r = i % (12 * 32), nb = r / 32, lane = r % 32;
        int k = kb * 8 + (lane & 3), n = nb * 8 + (lane >> 2);
        g_Bs[i] = packtf(comb_s(k, n, Wls, W000, W110, w00, w11),
                         comb_s(k + 4, n, Wls, W000, W110, w00, w11));
    } else if (i < NSZ + V1Z) {
        int j = i - NSZ;
        int kb = j / (4 * 32), r = j % (4 * 32), nb = r / 32, lane = r % 32;
        int k = kb * 8 + (lane & 3), n = nb * 8 + (lane >> 2);
        g_B1[j] = packtf(comb_1(k, n, Wlv, W011, w01),
                         comb_1(k + 4, n, Wlv, W011, w01));
    } else if (i < NSZ + V1Z + V2Z) {
        int j = i - NSZ - V1Z;
        int kb = j / (4 * 32), r = j % (4 * 32), nb = r / 32, lane = r % 32;
        int k = kb * 8 + (lane & 3), n = nb * 8 + (lane >> 2);
        g_B2[j] = packtf(comb_2(k, n, Wlv, W101, w10),
                         comb_2(k + 4, n, Wlv, W101, w10));
    }
}

// ---------------------------------------------------------------------------
// Kernel 2: zero the segment-sum buffer
// ---------------------------------------------------------------------------
__global__ void zero_msg(int n4)
{
    int i = blockIdx.x * blockDim.x + threadIdx.x;
    if (i < n4) reinterpret_cast<float4*>(g_msg)[i] = make_float4(0.f, 0.f, 0.f, 0.f);
}

// ---------------------------------------------------------------------------
// Kernel 3: scatter-add edge messages (vector global reductions)
// ---------------------------------------------------------------------------
__global__ void scatter_edges(const float4* __restrict__ em,
                              const int*    __restrict__ eidx,
                              int E)
{
    int i = blockIdx.x * blockDim.x + threadIdx.x;
    if (i >= E * 40) return;
    int e = i / 40;
    int j = i - e * 40;
    float4 v = __ldcs(em + i);
    int dst  = __ldg(eidx + E + e);
    float* p = g_msg + (size_t)dst * DIM + j * 4;
    asm volatile("red.global.add.v4.f32 [%0], {%1, %2, %3, %4};"
                 :: "l"(p), "f"(v.x), "f"(v.y), "f"(v.z), "f"(v.w)
                 : "memory");
}

// ---------------------------------------------------------------------------
// Kernel 4: fused per-node update, tensor-core (mma.sync m16n8k8 tf32).
// 512 threads = 16 warps, 64 nodes/CTA. Warp w: M-tile = w%4 (16 nodes),
// n0 = w/4. s-path N-tiles {n0, n0+4, n0+8}; the n0+8 tile is exactly the
// gate block for this warp's v columns (wc = 8*n0..8*n0+7) -> all epilogue
// combining happens in registers.
// U layout per node (tf32-rounded fp32, row-major stride USTRIDE):
//   [  0:192) U_s  = [a_s*ms | (mv.a_v)/sqrt3 | a_s*xs | (xv.a_v)/sqrt3]
//   [192:320) U_1  = [ms | xs]
//   [320+64c : 384+64c) = [a_s*mv[:,c] (32) | a_s*xv[:,c] (32)]  c=0..2
// ---------------------------------------------------------------------------
__global__ void __launch_bounds__(512, 1)
node_update(const float* __restrict__ feats,
            const float* __restrict__ attrs,
            float*       __restrict__ out,
            int N)
{
    extern __shared__ __align__(16) float sm[];
    float* sU  = sm;                  // 64 * USTRIDE floats
    float* sAv = sm + 64 * USTRIDE;   // 64 * 3

    const float rs5  = 0.44721359549995794f;  // 1/sqrt(5)
    const float inv3 = 0.5773502691896258f;   // 1/sqrt(3)

    const int t    = threadIdx.x;
    const int base = blockIdx.x * 64;

    // ---- prologue: build tf32-rounded U (8 threads per node) ----
    {
        int i  = t >> 3;
        int t8 = t & 7;
        int n  = base + i;
        float* u = sU + i * USTRIDE;
        if (n < N) {
            float a0  = __ldg(attrs + n * 4 + 0);
            float av0 = __ldg(attrs + n * 4 + 1);
            float av1 = __ldg(attrs + n * 4 + 2);
            float av2 = __ldg(attrs + n * 4 + 3);
            if (t8 == 0) {
                sAv[i * 3 + 0] = av0; sAv[i * 3 + 1] = av1; sAv[i * 3 + 2] = av2;
            }
            const float* mrow = g_msg + (size_t)n * DIM;
            const float* frow = feats + (size_t)n * DIM;
            #pragma unroll
            for (int k = t8; k < 64; k += 8) {
                float ms = mrow[k] * rs5;
                float xs = __ldcs(frow + k);
                u[k]       = tf32f(a0 * ms);
                u[96 + k]  = tf32f(a0 * xs);
                u[192 + k] = tf32f(ms);
                u[256 + k] = tf32f(xs);
            }
            #pragma unroll
            for (int k = t8; k < 32; k += 8) {
                float m0 = mrow[64 + k * 3 + 0] * rs5;
                float m1 = mrow[64 + k * 3 + 1] * rs5;
                float m2 = mrow[64 + k * 3 + 2] * rs5;
                float x0 = __ldcs(frow + 64 + k * 3 + 0);
                float x1 = __ldcs(frow + 64 + k * 3 + 1);
                float x2 = __ldcs(frow + 64 + k * 3 + 2);
                u[64 + k]  = tf32f((m0 * av0 + m1 * av1 + m2 * av2) * inv3);
                u[160 + k] = tf32f((x0 * av0 + x1 * av1 + x2 * av2) * inv3);
                u[320 + k] = tf32f(a0 * m0);   // c=0 mv
                u[384 + k] = tf32f(a0 * m1);   // c=1 mv
                u[448 + k] = tf32f(a0 * m2);   // c=2 mv
                u[352 + k] = tf32f(a0 * x0);   // c=0 xv
                u[416 + k] = tf32f(a0 * x1);   // c=1 xv
                u[480 + k] = tf32f(a0 * x2);   // c=2 xv
            }
        } else {
            #pragma unroll
            for (int k = t8; k < 512; k += 8) u[k] = 0.f;
            if (t8 == 0) { sAv[i*3] = 0.f; sAv[i*3+1] = 0.f; sAv[i*3+2] = 0.f; }
        }
    }
    __syncthreads();

    const int lane = t & 31;
    const int w    = t >> 5;
    const int mt   = w & 3;          // M-tile (16 nodes)
    const int n0   = w >> 2;         // 0..3
    const int gid  = lane >> 2;
    const int tid  = lane & 3;
    const int rA   = (mt * 16 + gid) * USTRIDE;       // A frag row 0 offset
    const int rB   = rA + 8 * USTRIDE;                // A frag row 8 offset
    const unsigned* uU = (const unsigned*)sU;

    // ---- s-path: 3 N-tiles, K=192 ----
    float sd0[4] = {0,0,0,0}, sd1[4] = {0,0,0,0}, sd2[4] = {0,0,0,0};
    #pragma unroll 4
    for (int kb = 0; kb < 24; ++kb) {
        int kc = kb * 8 + tid;
        unsigned a0 = uU[rA + kc],     a1 = uU[rB + kc];
        unsigned a2 = uU[rA + kc + 4], a3 = uU[rB + kc + 4];
        ull b0 = __ldg(g_Bs + (kb * 12 + n0) * 32 + lane);
        ull b1 = __ldg(g_Bs + (kb * 12 + n0 + 4) * 32 + lane);
        ull b2 = __ldg(g_Bs + (kb * 12 + n0 + 8) * 32 + lane);
        MMA8(sd0, a0, a1, a2, a3, b0);
        MMA8(sd1, a0, a1, a2, a3, b1);
        MMA8(sd2, a0, a1, a2, a3, b2);
    }

    // ---- v1: G1 = U_1 . Wc1, K=128, N-tile n0 ----
    float vd[4] = {0,0,0,0};
    #pragma unroll 4
    for (int kb = 0; kb < 16; ++kb) {
        int kc = 192 + kb * 8 + tid;
        unsigned a0 = uU[rA + kc],     a1 = uU[rB + kc];
        unsigned a2 = uU[rA + kc + 4], a3 = uU[rB + kc + 4];
        ull b = __ldg(g_B1 + (kb * 4 + n0) * 32 + lane);
        MMA8(vd, a0, a1, a2, a3, b);
    }

    // ---- v2: G2_c = U_2c . Wc2, K=64 per channel, N-tile n0 ----
    float pd0[4] = {0,0,0,0}, pd1[4] = {0,0,0,0}, pd2[4] = {0,0,0,0};
    #pragma unroll 2
    for (int kb = 0; kb < 8; ++kb) {
        ull b = __ldg(g_B2 + (kb * 4 + n0) * 32 + lane);
        int kc0 = 320 + kb * 8 + tid;
        unsigned a0, a1, a2, a3;
        a0 = uU[rA + kc0];       a1 = uU[rB + kc0];
        a2 = uU[rA + kc0 + 4];   a3 = uU[rB + kc0 + 4];
        MMA8(pd0, a0, a1, a2, a3, b);
        a0 = uU[rA + kc0 + 64];  a1 = uU[rB + kc0 + 64];
        a2 = uU[rA + kc0 + 68];  a3 = uU[rB + kc0 + 68];
        MMA8(pd1, a0, a1, a2, a3, b);
        a0 = uU[rA + kc0 + 128]; a1 = uU[rB + kc0 + 128];
        a2 = uU[rA + kc0 + 132]; a3 = uU[rB + kc0 + 132];
        MMA8(pd2, a0, a1, a2, a3, b);
    }

    // ---- epilogue: all combining in registers ----
    const int nvalid = N - base;
    #pragma unroll
    for (int r = 0; r < 2; ++r) {
        int slot = mt * 16 + gid + 8 * r;
        if (slot < nvalid) {
            float* orow = out + (size_t)(base + slot) * DIM;
            // out_s: silu of s-tiles 0,1
            float x0 = sd0[2*r], x1 = sd0[2*r+1];
            float y0 = sd1[2*r], y1 = sd1[2*r+1];
            *(float2*)(orow + 8 * n0 + 2 * tid) =
                make_float2(x0 / (1.f + __expf(-x0)), x1 / (1.f + __expf(-x1)));
            *(float2*)(orow + 32 + 8 * n0 + 2 * tid) =
                make_float2(y0 / (1.f + __expf(-y0)), y1 / (1.f + __expf(-y1)));
            // gates from s-tile 2; v outputs for wc = 8*n0 + 2*tid + {0,1}
            float g0 = 1.f / (1.f + __expf(-sd2[2*r]));
            float g1 = 1.f / (1.f + __expf(-sd2[2*r+1]));
            float av0 = sAv[slot * 3 + 0];
            float av1 = sAv[slot * 3 + 1];
            float av2 = sAv[slot * 3 + 2];
            float j0c0 = g0 * fmaf(vd[2*r],   av0, pd0[2*r]);
            float j0c1 = g0 * fmaf(vd[2*r],   av1, pd1[2*r]);
            float j0c2 = g0 * fmaf(vd[2*r],   av2, pd2[2*r]);
            float j1c0 = g1 * fmaf(vd[2*r+1], av0, pd0[2*r+1]);
            float j1c1 = g1 * fmaf(vd[2*r+1], av1, pd1[2*r+1]);
            float j1c2 = g1 * fmaf(vd[2*r+1], av2, pd2[2*r+1]);
            float* vout = orow + NS + (8 * n0 + 2 * tid) * 3;
            *(float2*)(vout + 0) = make_float2(j0c0, j0c1);
            *(float2*)(vout + 2) = make_float2(j0c2, j1c0);
            *(float2*)(vout + 4) = make_float2(j1c1, j1c2);
        }
    }
}

// ---------------------------------------------------------------------------
extern "C" void kernel_launch(void* const* d_in, const int* in_sizes, int n_in,
                              void* d_out, int out_size)
{
    const float* feats = (const float*)d_in[0];
    const float* attrs = (const float*)d_in[1];
    const float* emsg  = (const float*)d_in[2];
    const int*   eidx  = (const int*)  d_in[3];
    const float* w00   = (const float*)d_in[4];
    const float* w01   = (const float*)d_in[5];
    const float* w10   = (const float*)d_in[6];
    const float* w11   = (const float*)d_in[7];
    const float* Wls   = (const float*)d_in[8];
    const float* Wlv   = (const float*)d_in[9];
    const float* W000  = (const float*)d_in[10];
    const float* W110  = (const float*)d_in[11];
    const float* W011  = (const float*)d_in[12];
    const float* W101  = (const float*)d_in[13];

    int N = in_sizes[0] / DIM;
    int E = in_sizes[2] / DIM;

    const int smem_bytes = 64 * USTRIDE * 4 + 64 * 3 * 4;  // 132864
    cudaFuncSetAttribute(node_update,
                         cudaFuncAttributeMaxDynamicSharedMemorySize, smem_bytes);

    int prep_elems = 24 * 12 * 32 + 16 * 4 * 32 + 8 * 4 * 32;  // 12288
    prep_weights<<<(prep_elems + 255) / 256, 256>>>(
        Wls, Wlv, W000, W110, W011, W101, w00, w01, w10, w11);

    int n4 = N * (DIM / 4);
    zero_msg<<<(n4 + 255) / 256, 256>>>(n4);

    long total = (long)E * 40;
    scatter_edges<<<(int)((total + 255) / 256), 256>>>(
        (const float4*)emsg, eidx, E);

    int blocks = (N + 63) / 64;
    node_update<<<blocks, 512, smem_bytes>>>(feats, attrs, (float*)d_out, N);
}